// round 10
// baseline (speedup 1.0000x reference)
#include <cuda_runtime.h>
#include <cuda_bf16.h>
#include <math.h>
#include <stdint.h>

// Problem constants (fixed by the reference)
#define BB 2048
#define EE 512
#define CC 16384
// TEMPERATURE=0.05 -> 1/T = 20; TAU=4 -> scale/TAU: same=0.25, diff=0.125
// ramp = (epoch/150) * 1.0 * 16

// ---------------- device scratch (no allocations allowed) ----------------
__device__ int8_t g_batq[BB * EE];                  // 1 MB
__device__ int8_t g_teaq[BB * EE];                  // 1 MB
__device__ int8_t g_cmq[(size_t)CC * EE];           // 8 MB (normalized class_map int8)
__device__ float  g_sbat[BB];                       // batch row scales
__device__ float  g_stea[BB];                       // teacher row scales
__device__ float  g_scm[CC];                        // class_map row scales (incl. norm)
__device__ float  g_sim[(size_t)BB * BB];           // 16 MB
__device__ float  g_tsim[(size_t)BB * BB];          // 16 MB
__device__ float  g_pm[(size_t)BB * 128];           // per-(row, Ntile) max logit
__device__ float  g_ps[(size_t)BB * 128];           // per-(row, Ntile) sumexp
__device__ float  g_inv[CC];                        // 1/||class_map_row||
__device__ float  g_lablogit[BB];                   // fp32 exact label logits
__device__ float  g_rowv[BB];                       // per-row (lse - label_logit)
__device__ float  g_kl[BB];                         // per-row KL
__device__ int    g_lab32[BB];                      // decoded labels

// ---------------- helpers ----------------
__device__ __forceinline__ void imma16832(int* c, const uint32_t* a, const uint32_t* b) {
    asm volatile(
        "mma.sync.aligned.m16n8k32.row.col.s32.s8.s8.s32 "
        "{%0,%1,%2,%3}, {%4,%5,%6,%7}, {%8,%9}, {%0,%1,%2,%3};\n"
        : "+r"(c[0]), "+r"(c[1]), "+r"(c[2]), "+r"(c[3])
        : "r"(a[0]), "r"(a[1]), "r"(a[2]), "r"(a[3]), "r"(b[0]), "r"(b[1]));
}

__device__ __forceinline__ void ldsm4(uint32_t* r, uint32_t saddr) {
    asm volatile("ldmatrix.sync.aligned.m8n8.x4.shared.b16 {%0,%1,%2,%3}, [%4];\n"
                 : "=r"(r[0]), "=r"(r[1]), "=r"(r[2]), "=r"(r[3]) : "r"(saddr));
}

__device__ __forceinline__ void cp16(uint32_t saddr, const void* gptr) {
    asm volatile("cp.async.cg.shared.global [%0], [%1], 16;\n" :: "r"(saddr), "l"(gptr));
}

__device__ __forceinline__ int8_t q8(float v, float r) {
    int q = __float2int_rn(v * r);
    q = q > 127 ? 127 : (q < -127 ? -127 : q);
    return (int8_t)q;
}

// ---------------- label decode (int32 vs int64 robust) ----------------
__global__ void k_labels(const int* __restrict__ raw) {
    __shared__ int is64;
    if (threadIdx.x == 0) {
        int ok = 1;
        for (int i = 0; i < 64; i++)
            if (raw[2 * i + 1] != 0) { ok = 0; break; }
        is64 = ok;
    }
    __syncthreads();
    int f = is64;
    for (int i = threadIdx.x; i < BB; i += blockDim.x)
        g_lab32[i] = f ? raw[2 * i] : raw[i];
}

// ---------------- class_map: row norm + normalized int8 quantize ----------------
__global__ void k_prep_cm(const float* __restrict__ cmap) {
    int c = blockIdx.x;                        // one block (128 thr) per row
    int t = threadIdx.x;
    const float4* row = (const float4*)(cmap + (size_t)c * EE);
    float4 v = row[t];                          // cols [4t, 4t+3]
    float ss = v.x * v.x + v.y * v.y + v.z * v.z + v.w * v.w;
    float am = fmaxf(fmaxf(fabsf(v.x), fabsf(v.y)), fmaxf(fabsf(v.z), fabsf(v.w)));
    #pragma unroll
    for (int o = 16; o; o >>= 1) {
        ss += __shfl_xor_sync(0xffffffffu, ss, o);
        am = fmaxf(am, __shfl_xor_sync(0xffffffffu, am, o));
    }
    __shared__ float sred[4], samx[4];
    if ((t & 31) == 0) { sred[t >> 5] = ss; samx[t >> 5] = am; }
    __syncthreads();
    float tot = sred[0] + sred[1] + sred[2] + sred[3];
    float vmax = fmaxf(fmaxf(samx[0], samx[1]), fmaxf(samx[2], samx[3]));
    float inv = 1.0f / sqrtf(tot);
    if (t == 0) {
        g_inv[c] = inv;
        g_scm[c] = vmax * inv * (1.0f / 127.0f);   // logit scale per row
    }
    float r = (vmax > 0.f) ? (127.0f / vmax) : 0.f;
    char4 q;
    q.x = q8(v.x, r); q.y = q8(v.y, r); q.z = q8(v.z, r); q.w = q8(v.w, r);
    *(char4*)(g_cmq + (size_t)c * EE + t * 4) = q;
}

// ---------------- batch/teacher -> per-row int8 (one warp per row) ----------------
__global__ void k_prep_vec(const float* __restrict__ batch, const float* __restrict__ teacher) {
    int widx = (blockIdx.x * blockDim.x + threadIdx.x) >> 5;   // 0..4095
    int lane = threadIdx.x & 31;
    if (widx >= 2 * BB) return;
    int rrow = (widx < BB) ? widx : (widx - BB);
    const float* src = (widx < BB) ? batch : teacher;
    int8_t* dst = (widx < BB) ? g_batq : g_teaq;
    float* sc = (widx < BB) ? g_sbat : g_stea;

    const float4* rp = (const float4*)(src + (size_t)rrow * EE);
    float4 vv[4];
    float am = 0.f;
    #pragma unroll
    for (int i = 0; i < 4; i++) {
        vv[i] = rp[lane + i * 32];
        am = fmaxf(am, fmaxf(fmaxf(fabsf(vv[i].x), fabsf(vv[i].y)),
                             fmaxf(fabsf(vv[i].z), fabsf(vv[i].w))));
    }
    #pragma unroll
    for (int o = 16; o; o >>= 1) am = fmaxf(am, __shfl_xor_sync(0xffffffffu, am, o));
    float r = (am > 0.f) ? (127.0f / am) : 0.f;
    if (lane == 0) sc[rrow] = am * (1.0f / 127.0f);
    char4 q[4];
    #pragma unroll
    for (int i = 0; i < 4; i++) {
        q[i].x = q8(vv[i].x, r); q[i].y = q8(vv[i].y, r);
        q[i].z = q8(vv[i].z, r); q[i].w = q8(vv[i].w, r);
    }
    // lane writes 16 consecutive bytes: elements [lane*4 + i*128 .. ] match vv layout
    #pragma unroll
    for (int i = 0; i < 4; i++)
        *(char4*)(dst + (size_t)rrow * EE + (lane + i * 32) * 4) = q[i];
}

// ---------------- exact fp32 label logit per row (one warp per row) ----------------
__global__ void k_lab(const float* __restrict__ batch, const float* __restrict__ cmap) {
    int gw = (blockIdx.x * blockDim.x + threadIdx.x) >> 5;
    int lane = threadIdx.x & 31;
    if (gw >= BB) return;
    int l = g_lab32[gw];
    const float4* br = (const float4*)(batch + (size_t)gw * EE);
    const float4* cr = (const float4*)(cmap + (size_t)l * EE);
    float s = 0.f;
    #pragma unroll
    for (int i = 0; i < 4; i++) {
        float4 b = br[lane + i * 32];
        float4 c = cr[lane + i * 32];
        s = fmaf(b.x, c.x, s); s = fmaf(b.y, c.y, s);
        s = fmaf(b.z, c.z, s); s = fmaf(b.w, c.w, s);
    }
    #pragma unroll
    for (int o = 16; o; o >>= 1) s += __shfl_xor_sync(0xffffffffu, s, o);
    if (lane == 0) g_lablogit[gw] = s * g_inv[l] * 20.0f;
}

// ---------------- int8 GEMM: C[M,N] = (X[M,K]*sx) . (Y[N,K]*sy)^T ----------------
// MODE 0: logits (x20), fused per-row (max, sumexp) partials
// MODE 1: sim  -> g_sim      MODE 2: tsim -> g_tsim
// 128x128 tile, BK=64 bytes, 4-stage cp.async ring, one __syncthreads per K-tile.
#define ST 4
#define ROWB 80                      // 64 data bytes + 16 pad (conflict-free ldmatrix)
#define STAGE_BYTES (128 * ROWB)     // 10240

template <int MODE>
__global__ void __launch_bounds__(256) k_gemm() {
    const int8_t *X, *Y;
    const float *sxp, *syp;
    float* Cg = nullptr;
    if constexpr (MODE == 0) { X = g_batq; Y = g_cmq; sxp = g_sbat; syp = g_scm; }
    else if constexpr (MODE == 1) { X = g_batq; Y = g_batq; sxp = g_sbat; syp = g_sbat; Cg = g_sim; }
    else { X = g_teaq; Y = g_teaq; sxp = g_stea; syp = g_stea; Cg = g_tsim; }

    extern __shared__ char dyn[];
    char* As = dyn;
    char* Bs = dyn + ST * STAGE_BYTES;
    __shared__ float ssx[128], ssy[128];
    __shared__ float2 red[128 * 4];

    const int tid = threadIdx.x, lane = tid & 31, wid = tid >> 5;
    const int wm = (wid >> 2) * 64, wn = (wid & 3) * 32;    // warp grid 2(m) x 4(n)
    const int bm = blockIdx.x * 128, bn = blockIdx.y * 128;

    if (tid < 128) ssx[tid] = sxp[bm + tid];
    else ssy[tid - 128] = syp[bn + tid - 128];

    int acc[4][4][4];
    #pragma unroll
    for (int i = 0; i < 4; i++)
        #pragma unroll
        for (int j = 0; j < 4; j++)
            #pragma unroll
            for (int k = 0; k < 4; k++) acc[i][j][k] = 0;

    const uint32_t aB = (uint32_t)__cvta_generic_to_shared(As);
    const uint32_t bB = (uint32_t)__cvta_generic_to_shared(Bs);

    // loader: thread -> row (tid>>1), 32-byte half (tid&1); 2 cp16 each for A and B
    const int lr = tid >> 1, lh = tid & 1;
    const uint32_t loff = (uint32_t)(lr * ROWB + lh * 32);

    auto load_tile = [&](int kt, int buf) {
        uint32_t ab = aB + (uint32_t)buf * STAGE_BYTES;
        uint32_t bb = bB + (uint32_t)buf * STAGE_BYTES;
        const int8_t* xs = X + (size_t)(bm + lr) * EE + kt + lh * 32;
        const int8_t* ys = Y + (size_t)(bn + lr) * EE + kt + lh * 32;
        cp16(ab + loff, xs);       cp16(ab + loff + 16, xs + 16);
        cp16(bb + loff, ys);       cp16(bb + loff + 16, ys + 16);
        asm volatile("cp.async.commit_group;\n");
    };

    // ldmatrix lane address components (byte units)
    const int aRow = (lane & 15), aColB = (lane >> 4) * 16;
    const int gq = lane >> 3;
    const int bRowBase = ((gq >> 1) << 3) + (lane & 7);
    const int bColB = (gq & 1) * 16;

    const int NT = EE / 64;   // 8 K-tiles of 64 bytes

    #pragma unroll
    for (int s = 0; s < ST - 1; s++) load_tile(s * 64, s);

    for (int t = 0; t < NT; t++) {
        asm volatile("cp.async.wait_group %0;\n" :: "n"(ST - 2));
        __syncthreads();
        if (t + ST - 1 < NT) load_tile((t + ST - 1) * 64, (t + ST - 1) % ST);
        else asm volatile("cp.async.commit_group;\n");

        const int buf = t % ST;
        uint32_t aBase = aB + (uint32_t)buf * STAGE_BYTES;
        uint32_t bBase = bB + (uint32_t)buf * STAGE_BYTES;
        #pragma unroll
        for (int ks = 0; ks < 2; ks++) {           // two k32 steps per 64-byte tile
            const int kb = ks * 32;
            uint32_t af[4][4], bf[4][2];
            #pragma unroll
            for (int im = 0; im < 4; im++) {
                int row = wm + im * 16 + aRow;
                ldsm4(af[im], aBase + (uint32_t)(row * ROWB + kb + aColB));
            }
            #pragma unroll
            for (int np = 0; np < 2; np++) {
                int nloc = wn + np * 16 + bRowBase;
                uint32_t rr[4];
                ldsm4(rr, bBase + (uint32_t)(nloc * ROWB + kb + bColB));
                bf[np * 2 + 0][0] = rr[0]; bf[np * 2 + 0][1] = rr[1];
                bf[np * 2 + 1][0] = rr[2]; bf[np * 2 + 1][1] = rr[3];
            }
            #pragma unroll
            for (int im = 0; im < 4; im++)
                #pragma unroll
                for (int in = 0; in < 4; in++)
                    imma16832(acc[im][in], af[im], bf[in]);
        }
    }
    __syncthreads();   // also orders ssx/ssy writes before epilogue reads

    if constexpr (MODE == 0) {
        // Fused epilogue: per-row (max, sumexp) of logits over this block's 128 cols.
        const int qrow = lane >> 2, qcol = lane & 3;
        #pragma unroll
        for (int im = 0; im < 4; im++) {
            #pragma unroll
            for (int h = 0; h < 2; h++) {
                int rloc = wm + im * 16 + qrow + 8 * h;
                float f = ssx[rloc] * 20.0f;
                float v[8];
                #pragma unroll
                for (int in = 0; in < 4; in++) {
                    int c0 = wn + in * 8 + qcol * 2;
                    v[in * 2 + 0] = (float)acc[im][in][2 * h]     * f * ssy[c0];
                    v[in * 2 + 1] = (float)acc[im][in][2 * h + 1] * f * ssy[c0 + 1];
                }
                float m = -1e30f;
                #pragma unroll
                for (int i = 0; i < 8; i++) m = fmaxf(m, v[i]);
                m = fmaxf(m, __shfl_xor_sync(0xffffffffu, m, 1));
                m = fmaxf(m, __shfl_xor_sync(0xffffffffu, m, 2));
                float s = 0.f;
                #pragma unroll
                for (int i = 0; i < 8; i++) s += expf(v[i] - m);
                s += __shfl_xor_sync(0xffffffffu, s, 1);
                s += __shfl_xor_sync(0xffffffffu, s, 2);
                if (qcol == 0) red[rloc * 4 + (wid & 3)] = make_float2(m, s);
            }
        }
        __syncthreads();
        if (tid < 128) {
            float M = -1e30f, S = 0.f;
            #pragma unroll
            for (int w = 0; w < 4; w++) {
                float2 p = red[tid * 4 + w];
                float Mn = fmaxf(M, p.x);
                S = S * expf(M - Mn) + p.y * expf(p.x - Mn);
                M = Mn;
            }
            size_t o = (size_t)(bm + tid) * 128 + blockIdx.y;
            g_pm[o] = M;
            g_ps[o] = S;
        }
    } else {
        #pragma unroll
        for (int im = 0; im < 4; im++) {
            int rloc = wm + im * 16 + (lane >> 2);
            float f0 = ssx[rloc], f1 = ssx[rloc + 8];
            #pragma unroll
            for (int in = 0; in < 4; in++) {
                int cl = wn + in * 8 + (lane & 3) * 2;
                float sy0 = ssy[cl], sy1 = ssy[cl + 1];
                size_t o0 = (size_t)(bm + rloc) * BB + bn + cl;
                *(float2*)(Cg + o0) =
                    make_float2((float)acc[im][in][0] * f0 * sy0,
                                (float)acc[im][in][1] * f0 * sy1);
                *(float2*)(Cg + o0 + (size_t)8 * BB) =
                    make_float2((float)acc[im][in][2] * f1 * sy0,
                                (float)acc[im][in][3] * f1 * sy1);
            }
        }
    }
}

#define GEMM_SMEM (2 * ST * STAGE_BYTES)   // 81920 B

// ---------------- merge per-row partials -> rank row value ----------------
__global__ void k_rank() {
    int gw = (blockIdx.x * blockDim.x + threadIdx.x) >> 5;
    int lane = threadIdx.x & 31;
    if (gw >= BB) return;
    const float* pm = g_pm + (size_t)gw * 128;
    const float* ps = g_ps + (size_t)gw * 128;
    float M = -1e30f, S = 0.f;
    #pragma unroll
    for (int i = 0; i < 4; i++) {
        float m2 = pm[lane + i * 32], s2 = ps[lane + i * 32];
        float Mn = fmaxf(M, m2);
        S = S * expf(M - Mn) + s2 * expf(m2 - Mn);
        M = Mn;
    }
    #pragma unroll
    for (int o = 16; o; o >>= 1) {
        float m2 = __shfl_xor_sync(0xffffffffu, M, o);
        float s2 = __shfl_xor_sync(0xffffffffu, S, o);
        float Mn = fmaxf(M, m2);
        S = S * expf(M - Mn) + s2 * expf(m2 - Mn);
        M = Mn;
    }
    if (lane == 0) g_rowv[gw] = M + logf(S) - g_lablogit[gw];
}

// ---------------- per-row KD KL ----------------
__global__ void k_kd() {
    int b = blockIdx.x, t = threadIdx.x;
    int labb = g_lab32[b];
    const float* sr = g_sim  + (size_t)b * BB;
    const float* tr = g_tsim + (size_t)b * BB;
    float Mx = -1e30f, Sx = 0.f, My = -1e30f, Sy = 0.f, U = 0.f;
    for (int j = t; j < BB; j += 256) {
        float sc = (g_lab32[j] == labb) ? 0.25f : 0.125f;  // scale/TAU
        float x = sr[j] * sc, y = tr[j] * sc;
        if (x <= Mx) Sx += expf(x - Mx);
        else { Sx = Sx * expf(Mx - x) + 1.f; Mx = x; }
        float d = y - x;
        if (y <= My) { float e = expf(y - My); Sy += e; U += e * d; }
        else { float r = expf(My - y); Sy = Sy * r + 1.f; U = U * r + d; My = y; }
    }
    __shared__ float sMx[256], sSx[256], sMy[256], sSy[256], sU[256];
    sMx[t] = Mx; sSx[t] = Sx; sMy[t] = My; sSy[t] = Sy; sU[t] = U;
    __syncthreads();
    for (int s = 128; s > 0; s >>= 1) {
        if (t < s) {
            float m2 = sMx[t + s], s2 = sSx[t + s];
            float Mn = fmaxf(sMx[t], m2);
            sSx[t] = sSx[t] * expf(sMx[t] - Mn) + s2 * expf(m2 - Mn);
            sMx[t] = Mn;
            float my2 = sMy[t + s], sy2 = sSy[t + s], u2 = sU[t + s];
            float Myn = fmaxf(sMy[t], my2);
            float r1 = expf(sMy[t] - Myn), r2 = expf(my2 - Myn);
            sSy[t] = sSy[t] * r1 + sy2 * r2;
            sU[t]  = sU[t]  * r1 + u2  * r2;
            sMy[t] = Myn;
        }
        __syncthreads();
    }
    if (t == 0) {
        float lsex = sMx[0] + logf(sSx[0]);
        float lsey = sMy[0] + logf(sSy[0]);
        g_kl[b] = sU[0] / sSy[0] + lsex - lsey;
    }
}

// ---------------- final deterministic reduction ----------------
__global__ void k_final(const int* __restrict__ epoch_raw, int have_epoch,
                        float* __restrict__ out, int out_size) {
    int t = threadIdx.x;
    float a = 0.f, b = 0.f;
    for (int i = t; i < BB; i += 256) { a += g_rowv[i]; b += g_kl[i]; }
    __shared__ float sa[256], sb[256];
    sa[t] = a; sb[t] = b;
    __syncthreads();
    for (int s = 128; s > 0; s >>= 1) {
        if (t < s) { sa[t] += sa[t + s]; sb[t] += sb[t + s]; }
        __syncthreads();
    }
    if (t == 0) {
        float ep = 75.0f;
        if (have_epoch) {
            int iv = epoch_raw[0];
            if (iv >= 0 && iv <= 1000000) ep = (float)iv;
            else ep = __int_as_float(iv);
        }
        float loss_rank = sa[0] * (1.0f / BB);
        float loss_kd   = sb[0] * (1.0f / BB);
        float ramp = (ep / 150.0f) * 16.0f;
        float loss = loss_rank + ramp * loss_kd;
        out[0] = loss;
        if (out_size > 1) out[1] = loss_rank;
        if (out_size > 2) out[2] = loss_kd;
    }
}

// ---------------- launch ----------------
extern "C" void kernel_launch(void* const* d_in, const int* in_sizes, int n_in,
                              void* d_out, int out_size) {
    const float* batch   = (const float*)d_in[0];
    const float* teacher = (const float*)d_in[1];
    const float* cmap    = (const float*)d_in[2];
    const int*   labraw  = (const int*)d_in[3];
    const int*   epochp  = (n_in >= 5) ? (const int*)d_in[4] : (const int*)d_in[3];
    int have_epoch = (n_in >= 5) ? 1 : 0;
    float* out = (float*)d_out;

    cudaFuncSetAttribute(k_gemm<0>, cudaFuncAttributeMaxDynamicSharedMemorySize, GEMM_SMEM);
    cudaFuncSetAttribute(k_gemm<1>, cudaFuncAttributeMaxDynamicSharedMemorySize, GEMM_SMEM);
    cudaFuncSetAttribute(k_gemm<2>, cudaFuncAttributeMaxDynamicSharedMemorySize, GEMM_SMEM);

    k_labels<<<1, 256>>>(labraw);
    k_prep_cm<<<CC, 128>>>(cmap);
    k_prep_vec<<<512, 256>>>(batch, teacher);    // 4096 warps: batch + teacher rows
    k_lab<<<BB / 8, 256>>>(batch, cmap);

    dim3 gL(BB / 128, CC / 128);                 // 16 x 128
    k_gemm<0><<<gL, 256, GEMM_SMEM>>>();
    dim3 gS(BB / 128, BB / 128);                 // 16 x 16
    k_gemm<1><<<gS, 256, GEMM_SMEM>>>();
    k_gemm<2><<<gS, 256, GEMM_SMEM>>>();

    k_rank<<<BB / 8, 256>>>();
    k_kd<<<BB, 256>>>();
    k_final<<<1, 256>>>(epochp, have_epoch, out, out_size);
}

// round 11
// speedup vs baseline: 1.8754x; 1.8754x over previous
#include <cuda_runtime.h>
#include <cuda_bf16.h>
#include <math.h>
#include <stdint.h>

// Problem constants (fixed by the reference)
#define BB 2048
#define EE 512
#define CC 16384
// TEMPERATURE=0.05 -> 1/T = 20; TAU=4 -> scale/TAU: same=0.25, diff=0.125
// ramp = (epoch/150) * 1.0 * 16

// ---------------- device scratch (no allocations allowed) ----------------
__device__ __nv_bfloat16 g_bat[BB * EE];            // 2 MB
__device__ __nv_bfloat16 g_tea[BB * EE];            // 2 MB
__device__ __nv_bfloat16 g_cmn[CC * EE];            // 16 MB (normalized class_map bf16)
__device__ float         g_pm[(size_t)BB * 128];    // per-(row, Ntile) max*20
__device__ float         g_ps[(size_t)BB * 128];    // per-(row, Ntile) sumexp
__device__ float         g_kMx[BB * 16], g_kSx[BB * 16];   // KD partials (student)
__device__ float         g_kMy[BB * 16], g_kSy[BB * 16];   // KD partials (teacher)
__device__ float         g_kU [BB * 16];
__device__ float         g_inv[CC];                 // 1/||class_map_row||
__device__ float         g_lablogit[BB];            // fp32 exact label logits
__device__ float         g_rowv[BB];                // per-row (lse - label_logit)
__device__ float         g_kl[BB];                  // per-row KL
__device__ int           g_lab32[BB];               // decoded labels

// ---------------- helpers ----------------
__device__ __forceinline__ void mma16816(float* c, const uint32_t* a, const uint32_t* b) {
    asm volatile(
        "mma.sync.aligned.m16n8k16.row.col.f32.bf16.bf16.f32 "
        "{%0,%1,%2,%3}, {%4,%5,%6,%7}, {%8,%9}, {%0,%1,%2,%3};\n"
        : "+f"(c[0]), "+f"(c[1]), "+f"(c[2]), "+f"(c[3])
        : "r"(a[0]), "r"(a[1]), "r"(a[2]), "r"(a[3]), "r"(b[0]), "r"(b[1]));
}

__device__ __forceinline__ void ldsm4(uint32_t* r, uint32_t saddr) {
    asm volatile("ldmatrix.sync.aligned.m8n8.x4.shared.b16 {%0,%1,%2,%3}, [%4];\n"
                 : "=r"(r[0]), "=r"(r[1]), "=r"(r[2]), "=r"(r[3]) : "r"(saddr));
}

__device__ __forceinline__ void cp16(uint32_t saddr, const void* gptr) {
    asm volatile("cp.async.cg.shared.global [%0], [%1], 16;\n" :: "r"(saddr), "l"(gptr));
}

// ---------------- label decode (int32 vs int64 robust) ----------------
__global__ void k_labels(const int* __restrict__ raw) {
    __shared__ int is64;
    if (threadIdx.x == 0) {
        int ok = 1;
        for (int i = 0; i < 64; i++)
            if (raw[2 * i + 1] != 0) { ok = 0; break; }
        is64 = ok;
    }
    __syncthreads();
    int f = is64;
    for (int i = threadIdx.x; i < BB; i += blockDim.x)
        g_lab32[i] = f ? raw[2 * i] : raw[i];
}

// ---------------- class_map: row norm + normalized bf16 convert ----------------
__global__ void k_prep_cm(const float* __restrict__ cmap) {
    int c = blockIdx.x;
    int t = threadIdx.x;
    const float4* row = (const float4*)(cmap + (size_t)c * EE);
    float4 v = row[t];
    float ss = v.x * v.x + v.y * v.y + v.z * v.z + v.w * v.w;
    #pragma unroll
    for (int o = 16; o; o >>= 1) ss += __shfl_xor_sync(0xffffffffu, ss, o);
    __shared__ float sred[4];
    if ((t & 31) == 0) sred[t >> 5] = ss;
    __syncthreads();
    float tot = sred[0] + sred[1] + sred[2] + sred[3];
    float inv = 1.0f / sqrtf(tot);
    if (t == 0) g_inv[c] = inv;
    __nv_bfloat162* drow = (__nv_bfloat162*)(g_cmn + (size_t)c * EE);
    drow[t * 2 + 0] = __floats2bfloat162_rn(v.x * inv, v.y * inv);
    drow[t * 2 + 1] = __floats2bfloat162_rn(v.z * inv, v.w * inv);
}

// ---------------- batch/teacher -> bf16 ----------------
__global__ void k_prep_vec(const float* __restrict__ batch, const float* __restrict__ teacher) {
    const int n = BB * EE / 4;
    for (int i = blockIdx.x * blockDim.x + threadIdx.x; i < n; i += gridDim.x * blockDim.x) {
        float4 b = ((const float4*)batch)[i];
        ((__nv_bfloat162*)g_bat)[i * 2 + 0] = __floats2bfloat162_rn(b.x, b.y);
        ((__nv_bfloat162*)g_bat)[i * 2 + 1] = __floats2bfloat162_rn(b.z, b.w);
        float4 s = ((const float4*)teacher)[i];
        ((__nv_bfloat162*)g_tea)[i * 2 + 0] = __floats2bfloat162_rn(s.x, s.y);
        ((__nv_bfloat162*)g_tea)[i * 2 + 1] = __floats2bfloat162_rn(s.z, s.w);
    }
}

// ---------------- exact fp32 label logit per row (one warp per row) ----------------
__global__ void k_lab(const float* __restrict__ batch, const float* __restrict__ cmap) {
    int gw = (blockIdx.x * blockDim.x + threadIdx.x) >> 5;
    int lane = threadIdx.x & 31;
    if (gw >= BB) return;
    int l = g_lab32[gw];
    const float4* br = (const float4*)(batch + (size_t)gw * EE);
    const float4* cr = (const float4*)(cmap + (size_t)l * EE);
    float s = 0.f;
    #pragma unroll
    for (int i = 0; i < 4; i++) {
        float4 b = br[lane + i * 32];
        float4 c = cr[lane + i * 32];
        s = fmaf(b.x, c.x, s); s = fmaf(b.y, c.y, s);
        s = fmaf(b.z, c.z, s); s = fmaf(b.w, c.w, s);
    }
    #pragma unroll
    for (int o = 16; o; o >>= 1) s += __shfl_xor_sync(0xffffffffu, s, o);
    if (lane == 0) g_lablogit[gw] = s * g_inv[l] * 20.0f;
}

// ---------------- logits GEMM (bf16) + fused per-row (max,sumexp) partials ----------------
// 128x128 tile, BK=32, 4-stage cp.async ring, one __syncthreads per K-tile.
#define ST 4
#define STAGE_ELTS (128 * 40)

__global__ void __launch_bounds__(256) k_gemm0() {
    const __nv_bfloat16* X = g_bat;
    const __nv_bfloat16* Y = g_cmn;

    extern __shared__ __nv_bfloat16 dyn[];
    __nv_bfloat16* As = dyn;
    __nv_bfloat16* Bs = dyn + ST * STAGE_ELTS;

    const int tid = threadIdx.x, lane = tid & 31, wid = tid >> 5;
    const int wm = (wid >> 2) * 64, wn = (wid & 3) * 32;
    const int bm = blockIdx.x * 128, bn = blockIdx.y * 128;

    float acc[4][4][4];
    #pragma unroll
    for (int i = 0; i < 4; i++)
        #pragma unroll
        for (int j = 0; j < 4; j++)
            #pragma unroll
            for (int k = 0; k < 4; k++) acc[i][j][k] = 0.f;

    const uint32_t aB = (uint32_t)__cvta_generic_to_shared(As);
    const uint32_t bB = (uint32_t)__cvta_generic_to_shared(Bs);

    const int lr = tid >> 2, lch = tid & 3;
    const uint32_t loff0 = (uint32_t)(lr * 40 + lch * 8) * 2;
    const uint32_t loff1 = (uint32_t)((lr + 64) * 40 + lch * 8) * 2;

    auto load_tile = [&](int kt, int buf) {
        uint32_t ab = aB + (uint32_t)buf * (STAGE_ELTS * 2);
        uint32_t bb = bB + (uint32_t)buf * (STAGE_ELTS * 2);
        const __nv_bfloat16* xs = X + (size_t)(bm + lr) * EE + kt + lch * 8;
        const __nv_bfloat16* ys = Y + (size_t)(bn + lr) * EE + kt + lch * 8;
        cp16(ab + loff0, xs);
        cp16(ab + loff1, xs + (size_t)64 * EE);
        cp16(bb + loff0, ys);
        cp16(bb + loff1, ys + (size_t)64 * EE);
        asm volatile("cp.async.commit_group;\n");
    };

    const int aRow = (lane & 15), aCol = (lane >> 4) * 8;
    const int gq = lane >> 3;
    const int bRowBase = ((gq >> 1) << 3) + (lane & 7);
    const int bCol = (gq & 1) << 3;

    const int NT = EE / 32;   // 16

    #pragma unroll
    for (int s = 0; s < ST - 1; s++) load_tile(s * 32, s);

    for (int t = 0; t < NT; t++) {
        asm volatile("cp.async.wait_group %0;\n" :: "n"(ST - 2));
        __syncthreads();
        if (t + ST - 1 < NT) load_tile((t + ST - 1) * 32, (t + ST - 1) % ST);
        else asm volatile("cp.async.commit_group;\n");

        const int buf = t % ST;
        uint32_t aBase = aB + (uint32_t)buf * (STAGE_ELTS * 2);
        uint32_t bBase = bB + (uint32_t)buf * (STAGE_ELTS * 2);
        #pragma unroll
        for (int ks = 0; ks < 2; ks++) {
            const int kk = ks * 16;
            uint32_t af[4][4], bf[4][2];
            #pragma unroll
            for (int im = 0; im < 4; im++) {
                int row = wm + im * 16 + aRow;
                ldsm4(af[im], aBase + (uint32_t)(row * 40 + kk + aCol) * 2);
            }
            #pragma unroll
            for (int np = 0; np < 2; np++) {
                int nloc = wn + np * 16 + bRowBase;
                uint32_t rr[4];
                ldsm4(rr, bBase + (uint32_t)(nloc * 40 + kk + bCol) * 2);
                bf[np * 2 + 0][0] = rr[0]; bf[np * 2 + 0][1] = rr[1];
                bf[np * 2 + 1][0] = rr[2]; bf[np * 2 + 1][1] = rr[3];
            }
            #pragma unroll
            for (int im = 0; im < 4; im++)
                #pragma unroll
                for (int in = 0; in < 4; in++)
                    mma16816(acc[im][in], af[im], bf[in]);
        }
    }

    // Fused epilogue: per-row (max, sumexp) of 20*acc over this block's 128 cols.
    __syncthreads();
    float2* red = (float2*)As;                // [128][4], 4 KB
    const int qrow = lane >> 2, qcol = lane & 3;
    #pragma unroll
    for (int im = 0; im < 4; im++) {
        #pragma unroll
        for (int h = 0; h < 2; h++) {
            float m = -1e30f;
            #pragma unroll
            for (int in = 0; in < 4; in++)
                m = fmaxf(m, fmaxf(acc[im][in][2 * h], acc[im][in][2 * h + 1]));
            m = fmaxf(m, __shfl_xor_sync(0xffffffffu, m, 1));
            m = fmaxf(m, __shfl_xor_sync(0xffffffffu, m, 2));
            float s = 0.f;
            #pragma unroll
            for (int in = 0; in < 4; in++) {
                s += __expf((acc[im][in][2 * h]     - m) * 20.0f);
                s += __expf((acc[im][in][2 * h + 1] - m) * 20.0f);
            }
            s += __shfl_xor_sync(0xffffffffu, s, 1);
            s += __shfl_xor_sync(0xffffffffu, s, 2);
            if (qcol == 0) {
                int rloc = wm + im * 16 + qrow + 8 * h;
                red[rloc * 4 + (wid & 3)] = make_float2(m * 20.0f, s);
            }
        }
    }
    __syncthreads();
    if (tid < 128) {
        float M = -1e30f, S = 0.f;
        #pragma unroll
        for (int w = 0; w < 4; w++) {
            float2 p = red[tid * 4 + w];
            float Mn = fmaxf(M, p.x);
            S = S * __expf(M - Mn) + p.y * __expf(p.x - Mn);
            M = Mn;
        }
        size_t o = (size_t)(bm + tid) * 128 + blockIdx.y;
        g_pm[o] = M;
        g_ps[o] = S;
    }
}

#define GEMM0_SMEM (2 * ST * STAGE_ELTS * (int)sizeof(__nv_bfloat16))   // 81920 B

// ---------------- fused sim+tsim GEMM + KD partials ----------------
// Each 128x128 block computes both bat*bat^T and tea*tea^T tiles and reduces
// them to per-(row, Ntile) KD 5-tuples (Mx,Sx,My,Sy,U). sim/tsim never hit DRAM.
#define ST2 3
#define PAN 10240                 // one 128x(32+pad) bf16 panel, bytes
#define SSTR (4 * PAN)            // 4 panels per stage

__global__ void __launch_bounds__(256) k_gemm12() {
    extern __shared__ __nv_bfloat16 dyn[];
    __shared__ float redMx[512], redSx[512], redMy[512], redSy[512], redU[512];
    __shared__ int slabr[128], slabc[128];

    const int tid = threadIdx.x, lane = tid & 31, wid = tid >> 5;
    const int wm = (wid >> 2) * 64, wn = (wid & 3) * 32;
    const int bm = blockIdx.x * 128, bn = blockIdx.y * 128;

    if (tid < 128) slabr[tid] = g_lab32[bm + tid];
    else slabc[tid - 128] = g_lab32[bn + tid - 128];

    float accS[4][4][4], accT[4][4][4];
    #pragma unroll
    for (int i = 0; i < 4; i++)
        #pragma unroll
        for (int j = 0; j < 4; j++)
            #pragma unroll
            for (int k = 0; k < 4; k++) { accS[i][j][k] = 0.f; accT[i][j][k] = 0.f; }

    const uint32_t base = (uint32_t)__cvta_generic_to_shared(dyn);

    // loader: thread -> row (tid>>1), 32B half (tid&1); 2 cp16 per panel
    const int lr = tid >> 1, lh = tid & 1;
    const uint32_t loff = (uint32_t)(lr * 80 + lh * 32);

    auto load_tile = [&](int kt, int buf) {
        uint32_t sb = base + (uint32_t)buf * SSTR;
        const __nv_bfloat16* s0 = g_bat + (size_t)(bm + lr) * EE + kt + lh * 16;
        const __nv_bfloat16* s1 = g_bat + (size_t)(bn + lr) * EE + kt + lh * 16;
        const __nv_bfloat16* s2 = g_tea + (size_t)(bm + lr) * EE + kt + lh * 16;
        const __nv_bfloat16* s3 = g_tea + (size_t)(bn + lr) * EE + kt + lh * 16;
        cp16(sb + loff, s0);              cp16(sb + loff + 16, s0 + 8);
        cp16(sb + PAN + loff, s1);        cp16(sb + PAN + loff + 16, s1 + 8);
        cp16(sb + 2 * PAN + loff, s2);    cp16(sb + 2 * PAN + loff + 16, s2 + 8);
        cp16(sb + 3 * PAN + loff, s3);    cp16(sb + 3 * PAN + loff + 16, s3 + 8);
        asm volatile("cp.async.commit_group;\n");
    };

    const int aRow = (lane & 15), aCol = (lane >> 4) * 8;
    const int gq = lane >> 3;
    const int bRowBase = ((gq >> 1) << 3) + (lane & 7);
    const int bCol = (gq & 1) << 3;

    const int NT = EE / 32;   // 16

    load_tile(0, 0);
    load_tile(32, 1);

    for (int t = 0; t < NT; t++) {
        asm volatile("cp.async.wait_group %0;\n" :: "n"(ST2 - 2));
        __syncthreads();
        if (t + ST2 - 1 < NT) load_tile((t + ST2 - 1) * 32, (t + ST2 - 1) % ST2);
        else asm volatile("cp.async.commit_group;\n");

        uint32_t sb = base + (uint32_t)(t % ST2) * SSTR;
        #pragma unroll
        for (int ks = 0; ks < 2; ks++) {
            const int kk = ks * 16;
            uint32_t afS[4][4], bfS[4][2], afT[4][4], bfT[4][2];
            #pragma unroll
            for (int im = 0; im < 4; im++) {
                int row = wm + im * 16 + aRow;
                uint32_t ro = (uint32_t)(row * 40 + kk + aCol) * 2;
                ldsm4(afS[im], sb + ro);
                ldsm4(afT[im], sb + 2 * PAN + ro);
            }
            #pragma unroll
            for (int np = 0; np < 2; np++) {
                int nloc = wn + np * 16 + bRowBase;
                uint32_t ro = (uint32_t)(nloc * 40 + kk + bCol) * 2;
                uint32_t rr[4];
                ldsm4(rr, sb + PAN + ro);
                bfS[np * 2 + 0][0] = rr[0]; bfS[np * 2 + 0][1] = rr[1];
                bfS[np * 2 + 1][0] = rr[2]; bfS[np * 2 + 1][1] = rr[3];
                ldsm4(rr, sb + 3 * PAN + ro);
                bfT[np * 2 + 0][0] = rr[0]; bfT[np * 2 + 0][1] = rr[1];
                bfT[np * 2 + 1][0] = rr[2]; bfT[np * 2 + 1][1] = rr[3];
            }
            #pragma unroll
            for (int im = 0; im < 4; im++)
                #pragma unroll
                for (int in = 0; in < 4; in++) {
                    mma16816(accS[im][in], afS[im], bfS[in]);
                    mma16816(accT[im][in], afT[im], bfT[in]);
                }
        }
    }
    __syncthreads();

    // KD partial epilogue: per-row over this block's 128 cols.
    const int qrow = lane >> 2, qcol = lane & 3;
    #pragma unroll
    for (int im = 0; im < 4; im++) {
        #pragma unroll
        for (int h = 0; h < 2; h++) {
            int rloc = wm + im * 16 + qrow + 8 * h;
            int labr = slabr[rloc];
            float xs[8], ys[8];
            float mx = -1e30f, my = -1e30f;
            #pragma unroll
            for (int in = 0; in < 4; in++) {
                #pragma unroll
                for (int e = 0; e < 2; e++) {
                    int cl = wn + in * 8 + qcol * 2 + e;
                    float sc = (slabc[cl] == labr) ? 0.25f : 0.125f;
                    float x = accS[im][in][2 * h + e] * sc;
                    float y = accT[im][in][2 * h + e] * sc;
                    xs[in * 2 + e] = x; ys[in * 2 + e] = y;
                    mx = fmaxf(mx, x); my = fmaxf(my, y);
                }
            }
            mx = fmaxf(mx, __shfl_xor_sync(0xffffffffu, mx, 1));
            mx = fmaxf(mx, __shfl_xor_sync(0xffffffffu, mx, 2));
            my = fmaxf(my, __shfl_xor_sync(0xffffffffu, my, 1));
            my = fmaxf(my, __shfl_xor_sync(0xffffffffu, my, 2));
            float sx = 0.f, sy = 0.f, U = 0.f;
            #pragma unroll
            for (int i = 0; i < 8; i++) {
                sx += __expf(xs[i] - mx);
                float e = __expf(ys[i] - my);
                sy += e;
                U += e * (ys[i] - xs[i]);
            }
            sx += __shfl_xor_sync(0xffffffffu, sx, 1);
            sx += __shfl_xor_sync(0xffffffffu, sx, 2);
            sy += __shfl_xor_sync(0xffffffffu, sy, 1);
            sy += __shfl_xor_sync(0xffffffffu, sy, 2);
            U  += __shfl_xor_sync(0xffffffffu, U, 1);
            U  += __shfl_xor_sync(0xffffffffu, U, 2);
            if (qcol == 0) {
                int o = rloc * 4 + (wid & 3);
                redMx[o] = mx; redSx[o] = sx;
                redMy[o] = my; redSy[o] = sy; redU[o] = U;
            }
        }
    }
    __syncthreads();
    if (tid < 128) {
        float Mx = -1e30f, Sx = 0.f, My = -1e30f, Sy = 0.f, U = 0.f;
        #pragma unroll
        for (int w = 0; w < 4; w++) {
            int o = tid * 4 + w;
            float mx2 = redMx[o], sx2 = redSx[o];
            float Mn = fmaxf(Mx, mx2);
            Sx = Sx * __expf(Mx - Mn) + sx2 * __expf(mx2 - Mn);
            Mx = Mn;
            float my2 = redMy[o], sy2 = redSy[o], u2 = redU[o];
            float Myn = fmaxf(My, my2);
            float r1 = __expf(My - Myn), r2 = __expf(my2 - Myn);
            Sy = Sy * r1 + sy2 * r2;
            U  = U  * r1 + u2  * r2;
            My = Myn;
        }
        int o = (bm + tid) * 16 + blockIdx.y;
        g_kMx[o] = Mx; g_kSx[o] = Sx;
        g_kMy[o] = My; g_kSy[o] = Sy; g_kU[o] = U;
    }
}

#define GEMM12_SMEM (ST2 * SSTR)   // 122880 B

// ---------------- merge rank partials -> per-row rank value ----------------
__global__ void k_rank() {
    int gw = (blockIdx.x * blockDim.x + threadIdx.x) >> 5;
    int lane = threadIdx.x & 31;
    if (gw >= BB) return;
    const float* pm = g_pm + (size_t)gw * 128;
    const float* ps = g_ps + (size_t)gw * 128;
    float M = -1e30f, S = 0.f;
    #pragma unroll
    for (int i = 0; i < 4; i++) {
        float m2 = pm[lane + i * 32], s2 = ps[lane + i * 32];
        float Mn = fmaxf(M, m2);
        S = S * __expf(M - Mn) + s2 * __expf(m2 - Mn);
        M = Mn;
    }
    #pragma unroll
    for (int o = 16; o; o >>= 1) {
        float m2 = __shfl_xor_sync(0xffffffffu, M, o);
        float s2 = __shfl_xor_sync(0xffffffffu, S, o);
        float Mn = fmaxf(M, m2);
        S = S * __expf(M - Mn) + s2 * __expf(m2 - Mn);
        M = Mn;
    }
    if (lane == 0) g_rowv[gw] = M + logf(S) - g_lablogit[gw];
}

// ---------------- merge KD partials (16 per row) -> per-row KL ----------------
__global__ void k_kdm() {
    int row = (blockIdx.x * blockDim.x + threadIdx.x) >> 5;
    int lane = threadIdx.x & 31;
    if (row >= BB) return;
    float Mx = -1e30f, Sx = 0.f, My = -1e30f, Sy = 0.f, U = 0.f;
    if (lane < 16) {
        int o = row * 16 + lane;
        Mx = g_kMx[o]; Sx = g_kSx[o];
        My = g_kMy[o]; Sy = g_kSy[o]; U = g_kU[o];
    }
    #pragma unroll
    for (int o = 16; o; o >>= 1) {
        float mx2 = __shfl_xor_sync(0xffffffffu, Mx, o);
        float sx2 = __shfl_xor_sync(0xffffffffu, Sx, o);
        float my2 = __shfl_xor_sync(0xffffffffu, My, o);
        float sy2 = __shfl_xor_sync(0xffffffffu, Sy, o);
        float u2  = __shfl_xor_sync(0xffffffffu, U, o);
        float Mn = fmaxf(Mx, mx2);
        Sx = Sx * __expf(Mx - Mn) + sx2 * __expf(mx2 - Mn);
        Mx = Mn;
        float Myn = fmaxf(My, my2);
        float r1 = __expf(My - Myn), r2 = __expf(my2 - Myn);
        Sy = Sy * r1 + sy2 * r2;
        U  = U  * r1 + u2  * r2;
        My = Myn;
    }
    if (lane == 0)
        g_kl[row] = U / Sy + (Mx + logf(Sx)) - (My + logf(Sy));
}

// ---------------- final deterministic reduction ----------------
__global__ void k_final(const int* __restrict__ epoch_raw, int have_epoch,
                        float* __restrict__ out, int out_size) {
    int t = threadIdx.x;
    float a = 0.f, b = 0.f;
    for (int i = t; i < BB; i += 256) { a += g_rowv[i]; b += g_kl[i]; }
    __shared__ float sa[256], sb[256];
    sa[t] = a; sb[t] = b;
    __syncthreads();
    for (int s = 128; s > 0; s >>= 1) {
        if (t < s) { sa[t] += sa[t + s]; sb[t] += sb[t + s]; }
        __syncthreads();
    }
    if (t == 0) {
        float ep = 75.0f;
        if (have_epoch) {
            int iv = epoch_raw[0];
            if (iv >= 0 && iv <= 1000000) ep = (float)iv;
            else ep = __int_as_float(iv);
        }
        float loss_rank = sa[0] * (1.0f / BB);
        float loss_kd   = sb[0] * (1.0f / BB);
        float ramp = (ep / 150.0f) * 16.0f;
        float loss = loss_rank + ramp * loss_kd;
        out[0] = loss;
        if (out_size > 1) out[1] = loss_rank;
        if (out_size > 2) out[2] = loss_kd;
    }
}

// ---------------- launch ----------------
extern "C" void kernel_launch(void* const* d_in, const int* in_sizes, int n_in,
                              void* d_out, int out_size) {
    const float* batch   = (const float*)d_in[0];
    const float* teacher = (const float*)d_in[1];
    const float* cmap    = (const float*)d_in[2];
    const int*   labraw  = (const int*)d_in[3];
    const int*   epochp  = (n_in >= 5) ? (const int*)d_in[4] : (const int*)d_in[3];
    int have_epoch = (n_in >= 5) ? 1 : 0;
    float* out = (float*)d_out;

    cudaFuncSetAttribute(k_gemm0,  cudaFuncAttributeMaxDynamicSharedMemorySize, GEMM0_SMEM);
    cudaFuncSetAttribute(k_gemm12, cudaFuncAttributeMaxDynamicSharedMemorySize, GEMM12_SMEM);

    k_labels<<<1, 256>>>(labraw);
    k_prep_cm<<<CC, 128>>>(cmap);
    k_prep_vec<<<512, 256>>>(batch, teacher);
    k_lab<<<BB / 8, 256>>>(batch, cmap);

    dim3 gL(BB / 128, CC / 128);                 // 16 x 128
    k_gemm0<<<gL, 256, GEMM0_SMEM>>>();
    dim3 gS(BB / 128, BB / 128);                 // 16 x 16
    k_gemm12<<<gS, 256, GEMM12_SMEM>>>();

    k_rank<<<BB / 8, 256>>>();
    k_kdm<<<BB / 8, 256>>>();
    k_final<<<1, 256>>>(epochp, have_epoch, out, out_size);
}